// round 15
// baseline (speedup 1.0000x reference)
#include <cuda_runtime.h>
#include <cuda_fp16.h>
#include <mma.h>
#include <math.h>
#include <stdint.h>

using namespace nvcuda;

#define BSZ    2
#define LSEQ   4096
#define NH     16
#define HD     128
#define NSTATE 256
#define CHUNK_ 256
#define NCH    16
#define NBB    4
#define DIN    2048
#define ZTOT   64

typedef __half hf;

// ---------------- static device scratch ----------------
__device__ float g_E2 [(size_t)NBB*NH*LSEQ];   // exp(cs_i - m(tile(i)))
__device__ float g_Wst[(size_t)NBB*NH*LSEQ];   // dt * exp(cs_last - cs)
__device__ float g_W0 [(size_t)NBB*NH*LSEQ];   // dt * exp(m0 - cs)
__device__ float g_W1 [(size_t)NBB*NH*LSEQ];   // dt * exp(m1 - cs)
__device__ float g_PS [ZTOT*NH*2];             // exp(m0), exp(m1)
__device__ float g_cd [ZTOT*NH];               // exp(cs_last)
__device__ float g_gate[(size_t)BSZ*LSEQ*NH];  // x@W^T + D
__device__ __align__(16) hf g_Wf [NH*DIN];     // W fp16
__device__ __align__(16) hf g_BCf[(size_t)BSZ*LSEQ*2*NSTATE];   // BC fp16 [b][t][512]
__device__ __align__(16) hf g_XW [(size_t)NBB*DIN*LSEQ];        // wst*x^T [bb][d][t]
__device__ __align__(16) hf g_XB1[(size_t)NBB*DIN*LSEQ];        // w1*x^T  [bb][d][t]
__device__ __align__(16) hf g_XB0[(size_t)NBB*DIN*LSEQ/2];      // w0*x^T  [bb][d][c][128]
__device__ __align__(16) hf g_Btf[(size_t)ZTOT*NSTATE*CHUNK_];  // B^T fp16 [z][n][k]
__device__ float g_CB [(size_t)ZTOT*CHUNK_*CHUNK_];             // fp32 CB (unmasked)
__device__ __align__(16) hf g_CBf[(size_t)ZTOT*CHUNK_*CHUNK_];  // masked CB fp16 [z][i][k]
__device__ float g_S  [(size_t)ZTOT*NH*HD*NSTATE];              // states fp32 [z][h][p][n]
__device__ __align__(16) hf g_Pf [(size_t)ZTOT*NH*HD*NSTATE];   // prev fp16 (raw carry, c>0)
__device__ __align__(16) hf g_ybuf[(size_t)NBB*NH*LSEQ*HD];     // y fp16 [bb][h][t][p]

__device__ __forceinline__ size_t src_row(int bb, int t) {
    return (size_t)(bb & 1) * LSEQ + (size_t)(bb < 2 ? t : (LSEQ - 1 - t));
}
__device__ __forceinline__ uint32_t smem_u32(const void* p) {
    uint32_t a;
    asm("{ .reg .u64 t; cvta.to.shared.u64 t, %1; cvt.u32.u64 %0, t; }" : "=r"(a) : "l"(p));
    return a;
}
__device__ __forceinline__ void cpa16(uint32_t s, const void* g) {
    asm volatile("cp.async.ca.shared.global [%0], [%1], 16;" :: "r"(s), "l"(g));
}

// ---- generic MRxNR fp16 GEMM: 64x64 warp tiles, 3-slot ring, stage-before-wait ----
template <int MR, int NR, bool HOUT, typename SRC>
__device__ __forceinline__ void gemmT(int nkb, SRC src,
                                      void* out0, void* out1, int ldOut,
                                      const float* esc0, const float* esc1,
                                      int midKb, float midS0, float midS1) {
    constexpr int WCN  = NR / 64;
    constexpr int NWARP = (MR / 64) * WCN;
    constexpr int NTHR = NWARP * 32;
    constexpr int SLOT = (MR + NR) * 40;     // halfs per slot
    extern __shared__ __align__(16) hf sm[];
    const int tid = threadIdx.x;
    const int warp = tid >> 5, wr = warp / WCN, wc = warp % WCN;
    const uint32_t sbase = smem_u32(sm);

    wmma::fragment<wmma::accumulator, 16, 16, 16, float> acc[4][4];
#pragma unroll
    for (int i = 0; i < 4; i++)
#pragma unroll
        for (int j = 0; j < 4; j++) wmma::fill_fragment(acc[i][j], 0.0f);

    auto stage = [&](int kb) {
        if (kb < nkb) {
            int s = kb % 3;
#pragma unroll
            for (int r = tid; r < MR + NR; r += NTHR) {
                const hf* g = (r < MR) ? src(0, r, kb) : src(1, r - MR, kb);
                uint32_t sa = sbase + (uint32_t)(s * SLOT + r * 40) * 2;
                cpa16(sa, g); cpa16(sa + 16, g + 8); cpa16(sa + 32, g + 16); cpa16(sa + 48, g + 24);
            }
        }
        asm volatile("cp.async.commit_group;" ::: "memory");
    };

    stage(0); stage(1);
    for (int kb = 0; kb < nkb; kb++) {
        stage(kb + 2);   // slot (kb-1)%3: reads sealed by prev iteration's trailing sync
        asm volatile("cp.async.wait_group 2;" ::: "memory");
        __syncthreads();
        if (HOUT && kb == midKb) {
            float s = (wc >= WCN / 2) ? midS1 : midS0;
#pragma unroll
            for (int i = 0; i < 4; i++)
#pragma unroll
                for (int j = 0; j < 4; j++)
#pragma unroll
                    for (int e = 0; e < acc[i][j].num_elements; e++)
                        acc[i][j].x[e] *= s;
        }
        const hf* base = sm + (kb % 3) * SLOT;
        const hf* baseB = base + MR * 40;
#pragma unroll
        for (int ks = 0; ks < 32; ks += 16) {
            wmma::fragment<wmma::matrix_a, 16, 16, 16, hf, wmma::row_major> af[4];
#pragma unroll
            for (int i = 0; i < 4; i++)
                wmma::load_matrix_sync(af[i], base + (wr * 64 + i * 16) * 40 + ks, 40);
            wmma::fragment<wmma::matrix_b, 16, 16, 16, hf, wmma::col_major> bf[4];
#pragma unroll
            for (int j = 0; j < 4; j++)
                wmma::load_matrix_sync(bf[j], baseB + (wc * 64 + j * 16) * 40 + ks, 40);
#pragma unroll
            for (int i = 0; i < 4; i++)
#pragma unroll
                for (int j = 0; j < 4; j++)
                    wmma::mma_sync(acc[i][j], af[i], bf[j], acc[i][j]);
        }
        __syncthreads();
    }

    if (HOUT) {
        // NR == 256: heads in col-bands [0,128) and [128,256)
        float* smf = (float*)sm;
        const int r0 = tid & 127, hcol = (tid >> 7) * 64;
#pragma unroll
        for (int half = 0; half < 2; half++) {
            if ((wc >> 1) == half) {
                int wcl = wc & 1;
#pragma unroll
                for (int i = 0; i < 4; i++)
#pragma unroll
                    for (int j = 0; j < 4; j++)
                        wmma::store_matrix_sync(smf + (size_t)(wr * 64 + i * 16) * 128 + wcl * 64 + j * 16,
                                                acc[i][j], 128, wmma::mem_row_major);
            }
            __syncthreads();
            const float* esc = half ? esc1 : esc0;
            hf* outp = half ? (hf*)out1 : (hf*)out0;
            float e = esc[r0];
            hf* orow = outp + (size_t)r0 * HD + hcol;
            const float* srow = smf + (size_t)r0 * 128 + hcol;
#pragma unroll
            for (int j = 0; j < 64; j += 8) {
                hf tmp[8];
#pragma unroll
                for (int u = 0; u < 8; u++) tmp[u] = __float2half_rn(srow[j + u] * e);
                *(uint4*)&orow[j] = *(uint4*)tmp;
            }
            __syncthreads();
        }
    } else {
#pragma unroll
        for (int i = 0; i < 4; i++)
#pragma unroll
            for (int j = 0; j < 4; j++)
                wmma::store_matrix_sync((float*)out0 + (size_t)(wr * 64 + i * 16) * ldOut + wc * 64 + j * 16,
                                        acc[i][j], ldOut, wmma::mem_row_major);
    }
}

#define SMEM_CB ((128+128)*40*2*3)   // 61440
#define SMEM_BG ((128+256)*40*2*3)   // 92160
#define SMEM_GA (NH*DIN*2)           // 65536 (W fp16)

// ---------------- K1: softplus, cumsum, exp factors ----------------
__global__ void k_pre(const float* __restrict__ dt, const float* __restrict__ A_log) {
    int c = blockIdx.x, h = blockIdx.y, bb = blockIdx.z;
    int i = threadIdx.x;
    int t = c * CHUNK_ + i;
    int trow = (bb < 2) ? t : (LSEQ - 1 - t);
    int ch   = (bb < 2) ? h : (h + NH);
    float dtv = dt[((size_t)(bb & 1) * LSEQ + trow) * (2 * NH) + ch];
    float ds  = (dtv > 20.f) ? dtv : log1pf(expf(dtv));
    float dA  = ds * (-expf(A_log[h]));
    __shared__ float s[CHUNK_];
    s[i] = dA;
    __syncthreads();
    for (int off = 1; off < CHUNK_; off <<= 1) {
        float tv = (i >= off) ? s[i - off] : 0.f;
        __syncthreads();
        s[i] += tv;
        __syncthreads();
    }
    float cs = s[i], cl = s[CHUNK_ - 1];
    float m0 = s[64], m1 = s[192];
    size_t basei = ((size_t)bb * NH + h) * LSEQ + t;
    g_E2 [basei] = expf(cs - ((i < 128) ? m0 : m1));
    g_Wst[basei] = ds * expf(cl - cs);
    g_W0 [basei] = ds * expf(m0 - cs);
    g_W1 [basei] = ds * expf(m1 - cs);
    if (i == 0) {
        int zh = (bb * NCH + c) * NH + h;
        g_cd[zh] = expf(cl);
        g_PS[zh * 2]     = expf(m0);
        g_PS[zh * 2 + 1] = expf(m1);
    }
}

// ---------------- split W -> fp16 ----------------
__global__ void k_wsplit(const float* __restrict__ W) {
    int i = blockIdx.x * 256 + threadIdx.x;
    g_Wf[i] = __float2half_rn(W[i]);
}

// ---------------- gate GEMV: g_gate[b,t,h] = x[b,t]·W[h] + D[h] ----------------
__global__ void __launch_bounds__(256) k_gate(const float* __restrict__ x,
                                              const float* __restrict__ Dp) {
    int b = blockIdx.y;
    int t0 = blockIdx.x * 64;
    extern __shared__ __align__(16) hf ws[];   // NH*DIN fp16 = 64KB
    for (int i = threadIdx.x; i < NH * DIN / 8; i += 256)
        ((uint4*)ws)[i] = ((const uint4*)g_Wf)[i];
    __syncthreads();
    int warp = threadIdx.x >> 5, lane = threadIdx.x & 31;
    for (int r = warp; r < 64; r += 8) {
        int t = t0 + r;
        const float* xr = x + ((size_t)b * LSEQ + t) * DIN;
        float xv[64];
#pragma unroll
        for (int j = 0; j < 64; j++) xv[j] = xr[lane + j * 32];
#pragma unroll
        for (int h = 0; h < NH; h++) {
            const hf* wr = ws + h * DIN;
            float acc = 0.f;
#pragma unroll
            for (int j = 0; j < 64; j++) acc += xv[j] * __half2float(wr[lane + j * 32]);
#pragma unroll
            for (int o = 16; o; o >>= 1) acc += __shfl_down_sync(0xFFFFFFFFu, acc, o);
            if (lane == 0) g_gate[((size_t)b * LSEQ + t) * NH + h] = acc + Dp[h];
        }
    }
}

// ---------------- split BC -> fp16 [b][t][512] ----------------
__global__ void k_split_bc(const float* __restrict__ BC) {
    size_t row = blockIdx.x + (size_t)blockIdx.y * LSEQ;
    int col = threadIdx.x * 4;
    float4 v = *(const float4*)(BC + row * (2 * NSTATE) + col);
    hf tmp[4] = {__float2half_rn(v.x), __float2half_rn(v.y),
                 __float2half_rn(v.z), __float2half_rn(v.w)};
    *(uint2*)&g_BCf[row * (2 * NSTATE) + col] = *(uint2*)tmp;
}

// ---------------- transpose + scale x -> XW/XB1/XB0 fp16 [bb][d][t] ----------------
__global__ void k_xsplit(const float* __restrict__ x) {
    int bb = blockIdx.z;
    int tB = blockIdx.x * 32, dB = blockIdx.y * 32;
    __shared__ float s[32][33];
    int lr = threadIdx.x >> 5, lc = threadIdx.x & 31;
#pragma unroll
    for (int j = 0; j < 4; j++)
        s[lr + j * 8][lc] = x[src_row(bb, tB + lr + j * 8) * DIN + dB + lc];
    __syncthreads();
    int t = tB + lc;
    int c = t >> 8, tk = t & 255;
#pragma unroll
    for (int j = 0; j < 4; j++) {
        int d = dB + lr + j * 8;
        int h = d >> 7;
        float v = s[lc][lr + j * 8];
        size_t si = ((size_t)bb * NH + h) * LSEQ + t;
        size_t oi = ((size_t)bb * DIN + d) * LSEQ + t;
        g_XW [oi] = __float2half_rn(v * g_Wst[si]);
        g_XB1[oi] = __float2half_rn(v * g_W1[si]);
        if (tk < 128)
            g_XB0[(((size_t)bb * DIN + d) * NCH + c) * 128 + tk] = __float2half_rn(v * g_W0[si]);
    }
}

// ---------------- transpose B -> Bt fp16 [z][n][k] ----------------
__global__ void k_btsplit(const float* __restrict__ BC) {
    int z = blockIdx.z;
    int c = z % NCH, bb = z / NCH;
    int kB = blockIdx.x * 32, nB = blockIdx.y * 32;
    __shared__ float s[32][33];
    int lr = threadIdx.x >> 5, lc = threadIdx.x & 31;
#pragma unroll
    for (int j = 0; j < 4; j++)
        s[lr + j * 8][lc] = BC[src_row(bb, c * CHUNK_ + kB + lr + j * 8) * (2 * NSTATE) + nB + lc];
    __syncthreads();
#pragma unroll
    for (int j = 0; j < 4; j++)
        g_Btf[((size_t)z * NSTATE + nB + lr + j * 8) * CHUNK_ + kB + lc] =
            __float2half_rn(s[lc][lr + j * 8]);
}

// ---------------- CB GEMM: g_CB[z][i][k] = sum_n C[i,n] B[k,n] ----------------
__global__ void __launch_bounds__(128, 2) k_cb() {
    int iT = blockIdx.x, kT = blockIdx.y, z = blockIdx.z;
    if (iT == 0 && kT == 1) return;   // fully-masked tile, never read
    int c = z % NCH, bb = z / NCH;
    auto src = [&](int tile, int row, int kb) -> const hf* {
        if (tile == 0)
            return g_BCf + src_row(bb, c * CHUNK_ + iT * 128 + row) * (2 * NSTATE) + NSTATE + kb * 32;
        return g_BCf + src_row(bb, c * CHUNK_ + kT * 128 + row) * (2 * NSTATE) + kb * 32;
    };
    gemmT<128, 128, false>(NSTATE / 32, src,
                           g_CB + ((size_t)z * CHUNK_ + iT * 128) * CHUNK_ + kT * 128, nullptr, CHUNK_,
                           nullptr, nullptr, -1, 1.f, 1.f);
}

// ---------------- mask + convert CB ----------------
__global__ void k_cbsplit() {
    int i = blockIdx.x, z = blockIdx.y;
    int k = threadIdx.x;
    size_t o = ((size_t)z * CHUNK_ + i) * CHUNK_ + k;
    g_CBf[o] = __float2half_rn((k <= i) ? g_CB[o] : 0.f);
}

// -------- states GEMM (head-paired): M=256 (2 heads' p), N=128 (nT half) --------
__global__ void __launch_bounds__(256, 1) k_states() {
    int nT = blockIdx.x, hp = blockIdx.y, z = blockIdx.z;
    int c = z % NCH, bb = z / NCH;
    auto src = [&](int tile, int row, int kb) -> const hf* {
        if (tile == 0)
            return g_XW + ((size_t)bb * DIN + hp * 256 + row) * LSEQ + c * CHUNK_ + kb * 32;
        return g_Btf + ((size_t)z * NSTATE + nT * 128 + row) * CHUNK_ + kb * 32;
    };
    gemmT<256, 128, false>(CHUNK_ / 32, src,
                           g_S + ((size_t)z * NH + 2 * hp) * HD * NSTATE + nT * 128, nullptr, NSTATE,
                           nullptr, nullptr, -1, 1.f, 1.f);
}

// ------- inter-chunk scan: g_S -> single raw prev fp16 (skip c=0 write) -------
__global__ void k_scan() {
    int idx = blockIdx.x * blockDim.x + threadIdx.x;
    int n = idx & (NSTATE - 1);
    int p = (idx >> 8) & (HD - 1);
    int h = (idx >> 15) & (NH - 1);
    int bb = idx >> 19;
    size_t rest = ((size_t)h * HD + p) * NSTATE + n;
    const size_t stride = (size_t)NH * HD * NSTATE;
    float carry = 0.f;
    for (int c = 0; c < NCH; c++) {
        int zh = (bb * NCH + c) * NH + h;
        size_t off = (size_t)(bb * NCH + c) * stride + rest;
        float sv = g_S[off];
        if (c > 0) g_Pf[off] = __float2half_rn(carry);
        carry = carry * g_cd[zh] + sv;
    }
}

// -------- y GEMM (head-paired): inter phase first (raw P), mid-scale, intra phase --------
__global__ void __launch_bounds__(256, 1) k_y() {
    int iT = blockIdx.x, hp = blockIdx.y, z = blockIdx.z;
    int c = z % NCH, bb = z / NCH;
    const int p0kb = iT ? 8 : 4;          // intra-chunk K blocks
    const int interKb = (c > 0) ? 8 : 0;  // inter phase only if prev != 0
    auto src = [&](int tile, int row, int kb) -> const hf* {
        if (kb < interKb) {               // phase A: inter-chunk, n contraction (raw prev)
            int n0 = kb * 32;
            if (tile == 0)
                return g_BCf + src_row(bb, c * CHUNK_ + iT * 128 + row) * (2 * NSTATE) + NSTATE + n0;
            return g_Pf + ((size_t)z * NH + 2 * hp) * HD * NSTATE + (size_t)row * NSTATE + n0;
        }
        int pk = kb - interKb;            // phase B: intra-chunk, k contraction
        if (tile == 0)
            return g_CBf + ((size_t)z * CHUNK_ + iT * 128 + row) * CHUNK_ + pk * 32;
        if (iT)
            return g_XB1 + ((size_t)bb * DIN + hp * 256 + row) * LSEQ + c * CHUNK_ + pk * 32;
        return g_XB0 + (((size_t)bb * DIN + hp * 256 + row) * NCH + c) * 128 + pk * 32;
    };
    int t0 = c * CHUNK_ + iT * 128;
    size_t hb = (size_t)(bb * NH + 2 * hp);
    int zh0 = ((bb * NCH + c) * NH + 2 * hp) * 2 + iT;
    gemmT<128, 256, true>(interKb + p0kb, src,
                          g_ybuf + (hb * LSEQ + t0) * HD,
                          g_ybuf + ((hb + 1) * LSEQ + t0) * HD, 0,
                          g_E2 + hb * LSEQ + t0,
                          g_E2 + (hb + 1) * LSEQ + t0,
                          (c > 0) ? interKb : -1, g_PS[zh0], g_PS[zh0 + 2]);
}

// ---------------- final combine (gate precomputed) ----------------
__global__ void k_final(const float* __restrict__ x, float* __restrict__ out) {
    int t = blockIdx.x, b = blockIdx.y;
    __shared__ float gate[NH];
    if (threadIdx.x < NH)
        gate[threadIdx.x] = g_gate[((size_t)b * LSEQ + t) * NH + threadIdx.x];
    __syncthreads();
    int tb = LSEQ - 1 - t;
    const float* xrow = x + ((size_t)b * LSEQ + t) * DIN;
    float* orow = out + ((size_t)b * LSEQ + t) * DIN;
    for (int d = threadIdx.x; d < DIN; d += 256) {
        int h = d >> 7, p = d & 127;
        float v = xrow[d] * gate[h];
        if (t > 0)
            v += __half2float(g_ybuf[((size_t)(b * NH + h) * LSEQ + (t - 1)) * HD + p]);
        if (tb > 0)
            v += __half2float(g_ybuf[((size_t)((b + 2) * NH + h) * LSEQ + (tb - 1)) * HD + p]);
        orow[d] = v;
    }
}

// ---------------- launch ----------------
extern "C" void kernel_launch(void* const* d_in, const int* in_sizes, int n_in,
                              void* d_out, int out_size) {
    const float* x     = (const float*)d_in[0];
    const float* BC    = (const float*)d_in[1];
    const float* dt    = (const float*)d_in[2];
    const float* A_log = (const float*)d_in[3];
    const float* Dv    = (const float*)d_in[4];
    const float* W     = (const float*)d_in[5];
    float* out = (float*)d_out;

    cudaFuncSetAttribute(k_cb,     cudaFuncAttributeMaxDynamicSharedMemorySize, SMEM_CB);
    cudaFuncSetAttribute(k_states, cudaFuncAttributeMaxDynamicSharedMemorySize, SMEM_BG);
    cudaFuncSetAttribute(k_y,      cudaFuncAttributeMaxDynamicSharedMemorySize, SMEM_BG);
    cudaFuncSetAttribute(k_gate,   cudaFuncAttributeMaxDynamicSharedMemorySize, SMEM_GA);

    k_pre     <<<dim3(NCH, NH, NBB), 256>>>(dt, A_log);
    k_wsplit  <<<NH * DIN / 256, 256>>>(W);
    k_gate    <<<dim3(LSEQ / 64, BSZ), 256, SMEM_GA>>>(x, Dv);
    k_split_bc<<<dim3(LSEQ, BSZ), 128>>>(BC);
    k_xsplit  <<<dim3(LSEQ / 32, DIN / 32, NBB), 256>>>(x);
    k_btsplit <<<dim3(8, 8, ZTOT), 256>>>(BC);
    k_cb      <<<dim3(2, 2, ZTOT), 128, SMEM_CB>>>();
    k_cbsplit <<<dim3(CHUNK_, ZTOT), 256>>>();
    k_states  <<<dim3(2, NH / 2, ZTOT), 256, SMEM_BG>>>();
    k_scan    <<<(NBB * NH * HD * NSTATE) / 256, 256>>>();
    k_y       <<<dim3(2, NH / 2, ZTOT), 256, SMEM_BG>>>();
    k_final   <<<dim3(LSEQ, BSZ), 256>>>(x, out);
}

// round 16
// speedup vs baseline: 1.0850x; 1.0850x over previous
#include <cuda_runtime.h>
#include <cuda_fp16.h>
#include <mma.h>
#include <math.h>
#include <stdint.h>

using namespace nvcuda;

#define BSZ    2
#define LSEQ   4096
#define NH     16
#define HD     128
#define NSTATE 256
#define CHUNK_ 256
#define NCH    16
#define NBB    4
#define DIN    2048
#define ZTOT   64
#define EPAD   132   // epilogue fp32 smem row stride (bank-conflict: 4-way, not 32-way)

typedef __half hf;

// ---------------- static device scratch ----------------
__device__ float g_E2 [(size_t)NBB*NH*LSEQ];   // exp(cs_i - m(tile(i)))
__device__ float g_Wst[(size_t)NBB*NH*LSEQ];   // dt * exp(cs_last - cs)
__device__ float g_W0 [(size_t)NBB*NH*LSEQ];   // dt * exp(m0 - cs)
__device__ float g_W1 [(size_t)NBB*NH*LSEQ];   // dt * exp(m1 - cs)
__device__ float g_PS [ZTOT*NH*2];             // exp(m0), exp(m1)
__device__ float g_cd [ZTOT*NH];               // exp(cs_last)
__device__ __align__(16) hf g_BCf[(size_t)BSZ*LSEQ*2*NSTATE];   // BC fp16 [b][t][512]
__device__ __align__(16) hf g_XW [(size_t)NBB*DIN*LSEQ];        // wst*x^T [bb][d][t]
__device__ __align__(16) hf g_XB1[(size_t)NBB*DIN*LSEQ];        // w1*x^T  [bb][d][t]
__device__ __align__(16) hf g_XB0[(size_t)NBB*DIN*LSEQ/2];      // w0*x^T  [bb][d][c][128]
__device__ __align__(16) hf g_Btf[(size_t)ZTOT*NSTATE*CHUNK_];  // B^T fp16 [z][n][k]
__device__ __align__(16) hf g_CBf[(size_t)ZTOT*CHUNK_*CHUNK_];  // masked CB fp16 [z][i][k]
__device__ __align__(16) hf g_Sh [(size_t)ZTOT*NH*HD*NSTATE];   // states fp16 [z][h][p][n]
__device__ __align__(16) hf g_Pf [(size_t)ZTOT*NH*HD*NSTATE];   // prev fp16 (raw carry, c>0)
__device__ __align__(16) hf g_ybuf[(size_t)NBB*NH*LSEQ*HD];     // y fp16 [bb][h][t][p]

__device__ __forceinline__ size_t src_row(int bb, int t) {
    return (size_t)(bb & 1) * LSEQ + (size_t)(bb < 2 ? t : (LSEQ - 1 - t));
}
__device__ __forceinline__ uint32_t smem_u32(const void* p) {
    uint32_t a;
    asm("{ .reg .u64 t; cvta.to.shared.u64 t, %1; cvt.u32.u64 %0, t; }" : "=r"(a) : "l"(p));
    return a;
}
__device__ __forceinline__ void cpa16(uint32_t s, const void* g) {
    asm volatile("cp.async.ca.shared.global [%0], [%1], 16;" :: "r"(s), "l"(g));
}

// ---- generic MRxNR fp16 GEMM: 64x64 warp tiles, 3-slot ring, stage-before-wait ----
// src(tile 0=A / 1=B, row, kb) -> pointer to 32 contiguous halfs.
// MODE 0: fp32 direct store.  MODE 1: k_y two-head fp16 (esc0/esc1 + per-warp mid-scale).
// MODE 2: plain fp16 via padded smem.  MODE 3: causal-masked fp16 via padded smem.
template <int MR, int NR, int MODE, typename SRC>
__device__ __forceinline__ void gemmT(int nkb, SRC src,
                                      void* out0, void* out1, int ldOut,
                                      const float* esc0, const float* esc1,
                                      int maskRow, int maskCol,
                                      int midKb, float midS0, float midS1) {
    constexpr int WCN  = NR / 64;
    constexpr int NWARP = (MR / 64) * WCN;
    constexpr int NTHR = NWARP * 32;
    constexpr int SLOT = (MR + NR) * 40;     // halfs per slot
    extern __shared__ __align__(16) hf sm[];
    const int tid = threadIdx.x;
    const int warp = tid >> 5, wr = warp / WCN, wc = warp % WCN;
    const uint32_t sbase = smem_u32(sm);

    wmma::fragment<wmma::accumulator, 16, 16, 16, float> acc[4][4];
#pragma unroll
    for (int i = 0; i < 4; i++)
#pragma unroll
        for (int j = 0; j < 4; j++) wmma::fill_fragment(acc[i][j], 0.0f);

    auto stage = [&](int kb) {
        if (kb < nkb) {
            int s = kb % 3;
#pragma unroll
            for (int r = tid; r < MR + NR; r += NTHR) {
                const hf* g = (r < MR) ? src(0, r, kb) : src(1, r - MR, kb);
                uint32_t sa = sbase + (uint32_t)(s * SLOT + r * 40) * 2;
                cpa16(sa, g); cpa16(sa + 16, g + 8); cpa16(sa + 32, g + 16); cpa16(sa + 48, g + 24);
            }
        }
        asm volatile("cp.async.commit_group;" ::: "memory");
    };

    stage(0); stage(1);
    for (int kb = 0; kb < nkb; kb++) {
        stage(kb + 2);   // slot (kb-1)%3: reads sealed by prev iteration's trailing sync
        asm volatile("cp.async.wait_group 2;" ::: "memory");
        __syncthreads();
        if (MODE == 1 && kb == midKb) {
            float s = (wc >= WCN / 2) ? midS1 : midS0;
#pragma unroll
            for (int i = 0; i < 4; i++)
#pragma unroll
                for (int j = 0; j < 4; j++)
#pragma unroll
                    for (int e = 0; e < acc[i][j].num_elements; e++)
                        acc[i][j].x[e] *= s;
        }
        const hf* base = sm + (kb % 3) * SLOT;
        const hf* baseB = base + MR * 40;
#pragma unroll
        for (int ks = 0; ks < 32; ks += 16) {
            wmma::fragment<wmma::matrix_a, 16, 16, 16, hf, wmma::row_major> af[4];
#pragma unroll
            for (int i = 0; i < 4; i++)
                wmma::load_matrix_sync(af[i], base + (wr * 64 + i * 16) * 40 + ks, 40);
            wmma::fragment<wmma::matrix_b, 16, 16, 16, hf, wmma::col_major> bf[4];
#pragma unroll
            for (int j = 0; j < 4; j++)
                wmma::load_matrix_sync(bf[j], baseB + (wc * 64 + j * 16) * 40 + ks, 40);
#pragma unroll
            for (int i = 0; i < 4; i++)
#pragma unroll
                for (int j = 0; j < 4; j++)
                    wmma::mma_sync(acc[i][j], af[i], bf[j], acc[i][j]);
        }
        __syncthreads();
    }

    if (MODE == 0) {
#pragma unroll
        for (int i = 0; i < 4; i++)
#pragma unroll
            for (int j = 0; j < 4; j++)
                wmma::store_matrix_sync((float*)out0 + (size_t)(wr * 64 + i * 16) * ldOut + wc * 64 + j * 16,
                                        acc[i][j], ldOut, wmma::mem_row_major);
    } else if (MODE == 1) {
        // NR == 256: heads in col-bands [0,128) and [128,256); padded stride EPAD
        float* smf = (float*)sm;
        const int r0 = tid & 127, hcol = (tid >> 7) * 64;
#pragma unroll
        for (int half = 0; half < 2; half++) {
            if ((wc >> 1) == half) {
                int wcl = wc & 1;
#pragma unroll
                for (int i = 0; i < 4; i++)
#pragma unroll
                    for (int j = 0; j < 4; j++)
                        wmma::store_matrix_sync(smf + (size_t)(wr * 64 + i * 16) * EPAD + wcl * 64 + j * 16,
                                                acc[i][j], EPAD, wmma::mem_row_major);
            }
            __syncthreads();
            const float* esc = half ? esc1 : esc0;
            hf* outp = half ? (hf*)out1 : (hf*)out0;
            float e = esc[r0];
            hf* orow = outp + (size_t)r0 * HD + hcol;
            const float* srow = smf + (size_t)r0 * EPAD + hcol;
#pragma unroll
            for (int j = 0; j < 64; j += 8) {
                hf tmp[8];
#pragma unroll
                for (int u = 0; u < 8; u++) tmp[u] = __float2half_rn(srow[j + u] * e);
                *(uint4*)&orow[j] = *(uint4*)tmp;
            }
            __syncthreads();
        }
    } else {
        // MODE 2/3: fp16 via padded smem staging (NR == 128)
        float* smf = (float*)sm;
#pragma unroll
        for (int i = 0; i < 4; i++)
#pragma unroll
            for (int j = 0; j < 4; j++)
                wmma::store_matrix_sync(smf + (size_t)(wr * 64 + i * 16) * EPAD + wc * 64 + j * 16,
                                        acc[i][j], EPAD, wmma::mem_row_major);
        __syncthreads();
#pragma unroll
        for (int r = tid; r < MR; r += NTHR) {
            hf* orow = (hf*)out0 + (size_t)r * ldOut;
            const float* srow = smf + (size_t)r * EPAD;
#pragma unroll
            for (int j = 0; j < 128; j += 8) {
                hf tmp[8];
#pragma unroll
                for (int u = 0; u < 8; u++) {
                    float v = srow[j + u];
                    if (MODE == 3 && (maskCol + j + u > maskRow + r)) v = 0.f;
                    tmp[u] = __float2half_rn(v);
                }
                *(uint4*)&orow[j] = *(uint4*)tmp;
            }
        }
    }
}

#define SMEM_CB 67584                         // max(61440 slots, 128*EPAD*4 epilogue)
#define SMEM_ST 135168                        // max(92160 slots, 256*EPAD*4 epilogue)
#define SMEM_YG 92160                         // slots (>= 128*EPAD*4 = 67584)

// ---------------- K1: softplus, cumsum, exp factors ----------------
__global__ void k_pre(const float* __restrict__ dt, const float* __restrict__ A_log) {
    int c = blockIdx.x, h = blockIdx.y, bb = blockIdx.z;
    int i = threadIdx.x;
    int t = c * CHUNK_ + i;
    int trow = (bb < 2) ? t : (LSEQ - 1 - t);
    int ch   = (bb < 2) ? h : (h + NH);
    float dtv = dt[((size_t)(bb & 1) * LSEQ + trow) * (2 * NH) + ch];
    float ds  = (dtv > 20.f) ? dtv : log1pf(expf(dtv));
    float dA  = ds * (-expf(A_log[h]));
    __shared__ float s[CHUNK_];
    s[i] = dA;
    __syncthreads();
    for (int off = 1; off < CHUNK_; off <<= 1) {
        float tv = (i >= off) ? s[i - off] : 0.f;
        __syncthreads();
        s[i] += tv;
        __syncthreads();
    }
    float cs = s[i], cl = s[CHUNK_ - 1];
    float m0 = s[64], m1 = s[192];
    size_t basei = ((size_t)bb * NH + h) * LSEQ + t;
    g_E2 [basei] = expf(cs - ((i < 128) ? m0 : m1));
    g_Wst[basei] = ds * expf(cl - cs);
    g_W0 [basei] = ds * expf(m0 - cs);
    g_W1 [basei] = ds * expf(m1 - cs);
    if (i == 0) {
        int zh = (bb * NCH + c) * NH + h;
        g_cd[zh] = expf(cl);
        g_PS[zh * 2]     = expf(m0);
        g_PS[zh * 2 + 1] = expf(m1);
    }
}

// ---------------- split BC -> fp16 [b][t][512] ----------------
__global__ void k_split_bc(const float* __restrict__ BC) {
    size_t row = blockIdx.x + (size_t)blockIdx.y * LSEQ;
    int col = threadIdx.x * 4;
    float4 v = *(const float4*)(BC + row * (2 * NSTATE) + col);
    hf tmp[4] = {__float2half_rn(v.x), __float2half_rn(v.y),
                 __float2half_rn(v.z), __float2half_rn(v.w)};
    *(uint2*)&g_BCf[row * (2 * NSTATE) + col] = *(uint2*)tmp;
}

// ---------------- transpose + scale x -> XW/XB1/XB0 fp16 [bb][d][t] ----------------
__global__ void k_xsplit(const float* __restrict__ x) {
    int bb = blockIdx.z;
    int tB = blockIdx.x * 32, dB = blockIdx.y * 32;
    __shared__ float s[32][33];
    int lr = threadIdx.x >> 5, lc = threadIdx.x & 31;
#pragma unroll
    for (int j = 0; j < 4; j++)
        s[lr + j * 8][lc] = x[src_row(bb, tB + lr + j * 8) * DIN + dB + lc];
    __syncthreads();
    int t = tB + lc;
    int c = t >> 8, tk = t & 255;
#pragma unroll
    for (int j = 0; j < 4; j++) {
        int d = dB + lr + j * 8;
        int h = d >> 7;
        float v = s[lc][lr + j * 8];
        size_t si = ((size_t)bb * NH + h) * LSEQ + t;
        size_t oi = ((size_t)bb * DIN + d) * LSEQ + t;
        g_XW [oi] = __float2half_rn(v * g_Wst[si]);
        g_XB1[oi] = __float2half_rn(v * g_W1[si]);
        if (tk < 128)
            g_XB0[(((size_t)bb * DIN + d) * NCH + c) * 128 + tk] = __float2half_rn(v * g_W0[si]);
    }
}

// ---------------- transpose B -> Bt fp16 [z][n][k] ----------------
__global__ void k_btsplit(const float* __restrict__ BC) {
    int z = blockIdx.z;
    int c = z % NCH, bb = z / NCH;
    int kB = blockIdx.x * 32, nB = blockIdx.y * 32;
    __shared__ float s[32][33];
    int lr = threadIdx.x >> 5, lc = threadIdx.x & 31;
#pragma unroll
    for (int j = 0; j < 4; j++)
        s[lr + j * 8][lc] = BC[src_row(bb, c * CHUNK_ + kB + lr + j * 8) * (2 * NSTATE) + nB + lc];
    __syncthreads();
#pragma unroll
    for (int j = 0; j < 4; j++)
        g_Btf[((size_t)z * NSTATE + nB + lr + j * 8) * CHUNK_ + kB + lc] =
            __float2half_rn(s[lc][lr + j * 8]);
}

// -------- CB GEMM: g_CBf[z][i][k] = mask * sum_n C[i,n] B[k,n] (fused fp16 epilogue) --------
__global__ void __launch_bounds__(128, 2) k_cb() {
    int iT = blockIdx.x, kT = blockIdx.y, z = blockIdx.z;
    if (iT == 0 && kT == 1) return;   // fully-masked tile, never read
    int c = z % NCH, bb = z / NCH;
    auto src = [&](int tile, int row, int kb) -> const hf* {
        if (tile == 0)
            return g_BCf + src_row(bb, c * CHUNK_ + iT * 128 + row) * (2 * NSTATE) + NSTATE + kb * 32;
        return g_BCf + src_row(bb, c * CHUNK_ + kT * 128 + row) * (2 * NSTATE) + kb * 32;
    };
    gemmT<128, 128, 3>(NSTATE / 32, src,
                       g_CBf + ((size_t)z * CHUNK_ + iT * 128) * CHUNK_ + kT * 128, nullptr, CHUNK_,
                       nullptr, nullptr, iT * 128, kT * 128, -1, 1.f, 1.f);
}

// -------- states GEMM (head-paired): fp16 out g_Sh --------
__global__ void __launch_bounds__(256, 1) k_states() {
    int nT = blockIdx.x, hp = blockIdx.y, z = blockIdx.z;
    int c = z % NCH, bb = z / NCH;
    auto src = [&](int tile, int row, int kb) -> const hf* {
        if (tile == 0)
            return g_XW + ((size_t)bb * DIN + hp * 256 + row) * LSEQ + c * CHUNK_ + kb * 32;
        return g_Btf + ((size_t)z * NSTATE + nT * 128 + row) * CHUNK_ + kb * 32;
    };
    gemmT<256, 128, 2>(CHUNK_ / 32, src,
                       g_Sh + ((size_t)z * NH + 2 * hp) * HD * NSTATE + nT * 128, nullptr, NSTATE,
                       nullptr, nullptr, 0, 0, -1, 1.f, 1.f);
}

// ------- inter-chunk scan: g_Sh -> single raw prev fp16 (skip c=0 write) -------
__global__ void k_scan() {
    int idx = blockIdx.x * blockDim.x + threadIdx.x;
    int n = idx & (NSTATE - 1);
    int p = (idx >> 8) & (HD - 1);
    int h = (idx >> 15) & (NH - 1);
    int bb = idx >> 19;
    size_t rest = ((size_t)h * HD + p) * NSTATE + n;
    const size_t stride = (size_t)NH * HD * NSTATE;
    float carry = 0.f;
    for (int c = 0; c < NCH; c++) {
        int zh = (bb * NCH + c) * NH + h;
        size_t off = (size_t)(bb * NCH + c) * stride + rest;
        float sv = __half2float(g_Sh[off]);
        if (c > 0) g_Pf[off] = __float2half_rn(carry);
        carry = carry * g_cd[zh] + sv;
    }
}

// -------- y GEMM (head-paired): inter phase first (raw P), mid-scale, intra phase --------
__global__ void __launch_bounds__(256, 1) k_y() {
    int iT = blockIdx.x, hp = blockIdx.y, z = blockIdx.z;
    int c = z % NCH, bb = z / NCH;
    const int p0kb = iT ? 8 : 4;          // intra-chunk K blocks
    const int interKb = (c > 0) ? 8 : 0;  // inter phase only if prev != 0
    auto src = [&](int tile, int row, int kb) -> const hf* {
        if (kb < interKb) {               // phase A: inter-chunk, n contraction (raw prev)
            int n0 = kb * 32;
            if (tile == 0)
                return g_BCf + src_row(bb, c * CHUNK_ + iT * 128 + row) * (2 * NSTATE) + NSTATE + n0;
            return g_Pf + ((size_t)z * NH + 2 * hp) * HD * NSTATE + (size_t)row * NSTATE + n0;
        }
        int pk = kb - interKb;            // phase B: intra-chunk, k contraction
        if (tile == 0)
            return g_CBf + ((size_t)z * CHUNK_ + iT * 128 + row) * CHUNK_ + pk * 32;
        if (iT)
            return g_XB1 + ((size_t)bb * DIN + hp * 256 + row) * LSEQ + c * CHUNK_ + pk * 32;
        return g_XB0 + (((size_t)bb * DIN + hp * 256 + row) * NCH + c) * 128 + pk * 32;
    };
    int t0 = c * CHUNK_ + iT * 128;
    size_t hb = (size_t)(bb * NH + 2 * hp);
    int zh0 = ((bb * NCH + c) * NH + 2 * hp) * 2 + iT;
    gemmT<128, 256, 1>(interKb + p0kb, src,
                       g_ybuf + (hb * LSEQ + t0) * HD,
                       g_ybuf + ((hb + 1) * LSEQ + t0) * HD, 0,
                       g_E2 + hb * LSEQ + t0,
                       g_E2 + (hb + 1) * LSEQ + t0,
                       0, 0,
                       (c > 0) ? interKb : -1, g_PS[zh0], g_PS[zh0 + 2]);
}

// ---------------- final combine (R14 version: in-kernel gate GEMV) ----------------
__global__ void k_final(const float* __restrict__ x, const float* __restrict__ W,
                        const float* __restrict__ Dp, float* __restrict__ out) {
    int t = blockIdx.x, b = blockIdx.y;
    __shared__ float xs[DIN];
    __shared__ float gate[NH];
    const float* xrow = x + ((size_t)b * LSEQ + t) * DIN;
    for (int d = threadIdx.x; d < DIN; d += 256) xs[d] = xrow[d];
    __syncthreads();
    int warp = threadIdx.x / 32, lane = threadIdx.x % 32;
#pragma unroll
    for (int hh = 0; hh < 2; hh++) {
        int h = warp * 2 + hh;
        const float* wrow = W + (size_t)h * DIN;
        float acc = 0.f;
        for (int d = lane; d < DIN; d += 32) acc += xs[d] * wrow[d];
#pragma unroll
        for (int o = 16; o; o >>= 1) acc += __shfl_down_sync(0xFFFFFFFFu, acc, o);
        if (lane == 0) gate[h] = acc + Dp[h];
    }
    __syncthreads();
    int tb = LSEQ - 1 - t;
    float* orow = out + ((size_t)b * LSEQ + t) * DIN;
    for (int d = threadIdx.x; d < DIN; d += 256) {
        int h = d >> 7, p = d & 127;
        float v = xs[d] * gate[h];
        if (t > 0)
            v += __half2float(g_ybuf[((size_t)(b * NH + h) * LSEQ + (t - 1)) * HD + p]);
        if (tb > 0)
            v += __half2float(g_ybuf[((size_t)((b + 2) * NH + h) * LSEQ + (tb - 1)) * HD + p]);
        orow[d] = v;
    }
}

// ---------------- launch ----------------
extern "C" void kernel_launch(void* const* d_in, const int* in_sizes, int n_in,
                              void* d_out, int out_size) {
    const float* x     = (const float*)d_in[0];
    const float* BC    = (const float*)d_in[1];
    const float* dt    = (const float*)d_in[2];
    const float* A_log = (const float*)d_in[3];
    const float* Dv    = (const float*)d_in[4];
    const float* W     = (const float*)d_in[5];
    float* out = (float*)d_out;

    cudaFuncSetAttribute(k_cb,     cudaFuncAttributeMaxDynamicSharedMemorySize, SMEM_CB);
    cudaFuncSetAttribute(k_states, cudaFuncAttributeMaxDynamicSharedMemorySize, SMEM_ST);
    cudaFuncSetAttribute(k_y,      cudaFuncAttributeMaxDynamicSharedMemorySize, SMEM_YG);

    k_pre     <<<dim3(NCH, NH, NBB), 256>>>(dt, A_log);
    k_split_bc<<<dim3(LSEQ, BSZ), 128>>>(BC);
    k_xsplit  <<<dim3(LSEQ / 32, DIN / 32, NBB), 256>>>(x);
    k_btsplit <<<dim3(8, 8, ZTOT), 256>>>(BC);
    k_cb      <<<dim3(2, 2, ZTOT), 128, SMEM_CB>>>();
    k_states  <<<dim3(2, NH / 2, ZTOT), 256, SMEM_ST>>>();
    k_scan    <<<(NBB * NH * HD * NSTATE) / 256, 256>>>();
    k_y       <<<dim3(2, NH / 2, ZTOT), 256, SMEM_YG>>>();
    k_final   <<<dim3(LSEQ, BSZ), 256>>>(x, W, Dv, out);
}

// round 17
// speedup vs baseline: 1.0910x; 1.0055x over previous
#include <cuda_runtime.h>
#include <cuda_fp16.h>
#include <mma.h>
#include <math.h>
#include <stdint.h>

using namespace nvcuda;

#define BSZ    2
#define LSEQ   4096
#define NH     16
#define HD     128
#define NSTATE 256
#define CHUNK_ 256
#define NCH    16
#define NBB    4
#define DIN    2048
#define ZTOT   64
#define EPAD   132   // epilogue fp32 smem row stride (4-way banks, not 32-way)

typedef __half hf;

// ---------------- static device scratch ----------------
__device__ float g_E2 [(size_t)NBB*NH*LSEQ];   // exp(cs_i - m(tile(i)))
__device__ float g_Wst[(size_t)NBB*NH*LSEQ];   // dt * exp(cs_last - cs)
__device__ float g_W0 [(size_t)NBB*NH*LSEQ];   // dt * exp(m0 - cs)
__device__ float g_W1 [(size_t)NBB*NH*LSEQ];   // dt * exp(m1 - cs)
__device__ float g_PS [ZTOT*NH*2];             // exp(m0), exp(m1)
__device__ float g_cd [ZTOT*NH];               // exp(cs_last)
__device__ __align__(16) hf g_BCf[(size_t)BSZ*LSEQ*2*NSTATE];   // BC fp16 [b][t][512]
__device__ __align__(16) hf g_XW [(size_t)NBB*DIN*LSEQ];        // wst*x^T [bb][d][t]
__device__ __align__(16) hf g_XB1[(size_t)NBB*DIN*LSEQ];        // w1*x^T  [bb][d][t]
__device__ __align__(16) hf g_XB0[(size_t)NBB*DIN*LSEQ/2];      // w0*x^T  [bb][d][c][128]
__device__ __align__(16) hf g_Btf[(size_t)ZTOT*NSTATE*CHUNK_];  // B^T fp16 [z][n][k]
__device__ __align__(16) hf g_CBf[(size_t)ZTOT*CHUNK_*CHUNK_];  // masked CB fp16 [z][i][k]
__device__ __align__(16) hf g_Sh [(size_t)ZTOT*NH*HD*NSTATE];   // states fp16 [z][h][p][n]
__device__ __align__(16) hf g_Pf [(size_t)ZTOT*NH*HD*NSTATE];   // prev fp16 (raw carry, c>0)
__device__ __align__(16) hf g_ybuf[(size_t)NBB*NH*LSEQ*HD];     // y fp16 [bb][h][t][p]

__device__ __forceinline__ size_t src_row(int bb, int t) {
    return (size_t)(bb & 1) * LSEQ + (size_t)(bb < 2 ? t : (LSEQ - 1 - t));
}
__device__ __forceinline__ uint32_t smem_u32(const void* p) {
    uint32_t a;
    asm("{ .reg .u64 t; cvta.to.shared.u64 t, %1; cvt.u32.u64 %0, t; }" : "=r"(a) : "l"(p));
    return a;
}
__device__ __forceinline__ void cpa16(uint32_t s, const void* g) {
    asm volatile("cp.async.ca.shared.global [%0], [%1], 16;" :: "r"(s), "l"(g));
}

// ---- generic MRxNR fp16 GEMM, WTMxWTN warp tiles, 3-slot ring, stage-before-wait ----
// src(tile 0=A / 1=B, row, kb) -> pointer to 32 contiguous halfs.
// MODE 1: k_y two-head fp16 (esc0/esc1 + per-warp mid-scale).
// MODE 2: plain fp16 via padded smem.  MODE 3: causal-masked fp16 via padded smem.
template <int MR, int NR, int WTM, int WTN, int MODE, typename SRC>
__device__ __forceinline__ void gemmT(int nkb, SRC src,
                                      void* out0, void* out1, int ldOut,
                                      const float* esc0, const float* esc1,
                                      int maskRow, int maskCol,
                                      int midKb, float midS0, float midS1) {
    constexpr int NWC  = NR / WTN;
    constexpr int NWARP = (MR / WTM) * NWC;
    constexpr int NTHR = NWARP * 32;
    constexpr int AM = WTM / 16, BN = WTN / 16;
    constexpr int SLOT = (MR + NR) * 40;     // halfs per slot
    extern __shared__ __align__(16) hf sm[];
    const int tid = threadIdx.x;
    const int warp = tid >> 5, wr = warp / NWC, wc = warp % NWC;
    const uint32_t sbase = smem_u32(sm);

    wmma::fragment<wmma::accumulator, 16, 16, 16, float> acc[AM][BN];
#pragma unroll
    for (int i = 0; i < AM; i++)
#pragma unroll
        for (int j = 0; j < BN; j++) wmma::fill_fragment(acc[i][j], 0.0f);

    auto stage = [&](int kb) {
        if (kb < nkb) {
            int s = kb % 3;
#pragma unroll
            for (int r = tid; r < MR + NR; r += NTHR) {
                const hf* g = (r < MR) ? src(0, r, kb) : src(1, r - MR, kb);
                uint32_t sa = sbase + (uint32_t)(s * SLOT + r * 40) * 2;
                cpa16(sa, g); cpa16(sa + 16, g + 8); cpa16(sa + 32, g + 16); cpa16(sa + 48, g + 24);
            }
        }
        asm volatile("cp.async.commit_group;" ::: "memory");
    };

    stage(0); stage(1);
    for (int kb = 0; kb < nkb; kb++) {
        stage(kb + 2);   // slot (kb-1)%3: reads sealed by prev iteration's trailing sync
        asm volatile("cp.async.wait_group 2;" ::: "memory");
        __syncthreads();
        if (MODE == 1 && kb == midKb) {
            float s = (wc >= NWC / 2) ? midS1 : midS0;
#pragma unroll
            for (int i = 0; i < AM; i++)
#pragma unroll
                for (int j = 0; j < BN; j++)
#pragma unroll
                    for (int e = 0; e < acc[i][j].num_elements; e++)
                        acc[i][j].x[e] *= s;
        }
        const hf* base = sm + (kb % 3) * SLOT;
        const hf* baseB = base + MR * 40;
#pragma unroll
        for (int ks = 0; ks < 32; ks += 16) {
            wmma::fragment<wmma::matrix_a, 16, 16, 16, hf, wmma::row_major> af[AM];
#pragma unroll
            for (int i = 0; i < AM; i++)
                wmma::load_matrix_sync(af[i], base + (wr * WTM + i * 16) * 40 + ks, 40);
            wmma::fragment<wmma::matrix_b, 16, 16, 16, hf, wmma::col_major> bf[BN];
#pragma unroll
            for (int j = 0; j < BN; j++)
                wmma::load_matrix_sync(bf[j], baseB + (wc * WTN + j * 16) * 40 + ks, 40);
#pragma unroll
            for (int i = 0; i < AM; i++)
#pragma unroll
                for (int j = 0; j < BN; j++)
                    wmma::mma_sync(acc[i][j], af[i], bf[j], acc[i][j]);
        }
        __syncthreads();
    }

    if (MODE == 1) {
        // NR == 256: heads in col-bands [0,128) and [128,256); padded stride EPAD
        float* smf = (float*)sm;
        const int r0 = tid & 127, hcol = (tid >> 7) * 64;
#pragma unroll
        for (int half = 0; half < 2; half++) {
            if ((wc * WTN) / 128 == half) {
                int wcl = (wc * WTN % 128) / WTN;
#pragma unroll
                for (int i = 0; i < AM; i++)
#pragma unroll
                    for (int j = 0; j < BN; j++)
                        wmma::store_matrix_sync(smf + (size_t)(wr * WTM + i * 16) * EPAD + wcl * WTN + j * 16,
                                                acc[i][j], EPAD, wmma::mem_row_major);
            }
            __syncthreads();
            const float* esc = half ? esc1 : esc0;
            hf* outp = half ? (hf*)out1 : (hf*)out0;
            float e = esc[r0];
            hf* orow = outp + (size_t)r0 * HD + hcol;
            const float* srow = smf + (size_t)r0 * EPAD + hcol;
#pragma unroll
            for (int j = 0; j < 64; j += 8) {
                hf tmp[8];
#pragma unroll
                for (int u = 0; u < 8; u++) tmp[u] = __float2half_rn(srow[j + u] * e);
                *(uint4*)&orow[j] = *(uint4*)tmp;
            }
            __syncthreads();
        }
    } else {
        // MODE 2/3: fp16 via padded smem staging (NR == 128)
        float* smf = (float*)sm;
#pragma unroll
        for (int i = 0; i < AM; i++)
#pragma unroll
            for (int j = 0; j < BN; j++)
                wmma::store_matrix_sync(smf + (size_t)(wr * WTM + i * 16) * EPAD + wc * WTN + j * 16,
                                        acc[i][j], EPAD, wmma::mem_row_major);
        __syncthreads();
#pragma unroll
        for (int r = tid; r < MR; r += NTHR) {
            hf* orow = (hf*)out0 + (size_t)r * ldOut;
            const float* srow = smf + (size_t)r * EPAD;
#pragma unroll
            for (int j = 0; j < 128; j += 8) {
                hf tmp[8];
#pragma unroll
                for (int u = 0; u < 8; u++) {
                    float v = srow[j + u];
                    if (MODE == 3 && (maskCol + j + u > maskRow + r)) v = 0.f;
                    tmp[u] = __float2half_rn(v);
                }
                *(uint4*)&orow[j] = *(uint4*)tmp;
            }
        }
    }
}

#define SMEM_MID 135168    // max(states slots 92160, 256*EPAD*4 epilogue)
#define SMEM_YG  92160     // k_y slots (>= 128*EPAD*4 = 67584)

// ---------------- K1: softplus, cumsum, exp factors ----------------
__global__ void k_pre(const float* __restrict__ dt, const float* __restrict__ A_log) {
    int c = blockIdx.x, h = blockIdx.y, bb = blockIdx.z;
    int i = threadIdx.x;
    int t = c * CHUNK_ + i;
    int trow = (bb < 2) ? t : (LSEQ - 1 - t);
    int ch   = (bb < 2) ? h : (h + NH);
    float dtv = dt[((size_t)(bb & 1) * LSEQ + trow) * (2 * NH) + ch];
    float ds  = (dtv > 20.f) ? dtv : log1pf(expf(dtv));
    float dA  = ds * (-expf(A_log[h]));
    __shared__ float s[CHUNK_];
    s[i] = dA;
    __syncthreads();
    for (int off = 1; off < CHUNK_; off <<= 1) {
        float tv = (i >= off) ? s[i - off] : 0.f;
        __syncthreads();
        s[i] += tv;
        __syncthreads();
    }
    float cs = s[i], cl = s[CHUNK_ - 1];
    float m0 = s[64], m1 = s[192];
    size_t basei = ((size_t)bb * NH + h) * LSEQ + t;
    g_E2 [basei] = expf(cs - ((i < 128) ? m0 : m1));
    g_Wst[basei] = ds * expf(cl - cs);
    g_W0 [basei] = ds * expf(m0 - cs);
    g_W1 [basei] = ds * expf(m1 - cs);
    if (i == 0) {
        int zh = (bb * NCH + c) * NH + h;
        g_cd[zh] = expf(cl);
        g_PS[zh * 2]     = expf(m0);
        g_PS[zh * 2 + 1] = expf(m1);
    }
}

// ---------------- split BC -> fp16 [b][t][512] ----------------
__global__ void k_split_bc(const float* __restrict__ BC) {
    size_t row = blockIdx.x + (size_t)blockIdx.y * LSEQ;
    int col = threadIdx.x * 4;
    float4 v = *(const float4*)(BC + row * (2 * NSTATE) + col);
    hf tmp[4] = {__float2half_rn(v.x), __float2half_rn(v.y),
                 __float2half_rn(v.z), __float2half_rn(v.w)};
    *(uint2*)&g_BCf[row * (2 * NSTATE) + col] = *(uint2*)tmp;
}

// ---------------- transpose + scale x -> XW/XB1/XB0 fp16 [bb][d][t] ----------------
__global__ void k_xsplit(const float* __restrict__ x) {
    int bb = blockIdx.z;
    int tB = blockIdx.x * 32, dB = blockIdx.y * 32;
    __shared__ float s[32][33];
    int lr = threadIdx.x >> 5, lc = threadIdx.x & 31;
#pragma unroll
    for (int j = 0; j < 4; j++)
        s[lr + j * 8][lc] = x[src_row(bb, tB + lr + j * 8) * DIN + dB + lc];
    __syncthreads();
    int t = tB + lc;
    int c = t >> 8, tk = t & 255;
#pragma unroll
    for (int j = 0; j < 4; j++) {
        int d = dB + lr + j * 8;
        int h = d >> 7;
        float v = s[lc][lr + j * 8];
        size_t si = ((size_t)bb * NH + h) * LSEQ + t;
        size_t oi = ((size_t)bb * DIN + d) * LSEQ + t;
        g_XW [oi] = __float2half_rn(v * g_Wst[si]);
        g_XB1[oi] = __float2half_rn(v * g_W1[si]);
        if (tk < 128)
            g_XB0[(((size_t)bb * DIN + d) * NCH + c) * 128 + tk] = __float2half_rn(v * g_W0[si]);
    }
}

// ---------------- transpose B -> Bt fp16 [z][n][k] ----------------
__global__ void k_btsplit(const float* __restrict__ BC) {
    int z = blockIdx.z;
    int c = z % NCH, bb = z / NCH;
    int kB = blockIdx.x * 32, nB = blockIdx.y * 32;
    __shared__ float s[32][33];
    int lr = threadIdx.x >> 5, lc = threadIdx.x & 31;
#pragma unroll
    for (int j = 0; j < 4; j++)
        s[lr + j * 8][lc] = BC[src_row(bb, c * CHUNK_ + kB + lr + j * 8) * (2 * NSTATE) + nB + lc];
    __syncthreads();
#pragma unroll
    for (int j = 0; j < 4; j++)
        g_Btf[((size_t)z * NSTATE + nB + lr + j * 8) * CHUNK_ + kB + lc] =
            __float2half_rn(s[lc][lr + j * 8]);
}

// -------- fused mid kernel: every 5th block = CB tile, rest = states tile --------
__global__ void __launch_bounds__(256, 1) k_mid() {
    int bx = blockIdx.x;
    if (bx % 5 == 4) {
        // CB GEMM: g_CBf[z][i][k] = mask * sum_n C[i,n] B[k,n]
        int idx = bx / 5;
        int iT = idx & 1, kT = (idx >> 1) & 1, z = idx >> 2;
        if (iT == 0 && kT == 1) return;   // fully-masked tile, never read
        int c = z % NCH, bb = z / NCH;
        auto src = [&](int tile, int row, int kb) -> const hf* {
            if (tile == 0)
                return g_BCf + src_row(bb, c * CHUNK_ + iT * 128 + row) * (2 * NSTATE) + NSTATE + kb * 32;
            return g_BCf + src_row(bb, c * CHUNK_ + kT * 128 + row) * (2 * NSTATE) + kb * 32;
        };
        gemmT<128, 128, 64, 32, 3>(NSTATE / 32, src,
                                   g_CBf + ((size_t)z * CHUNK_ + iT * 128) * CHUNK_ + kT * 128,
                                   nullptr, CHUNK_,
                                   nullptr, nullptr, iT * 128, kT * 128, -1, 1.f, 1.f);
    } else {
        // states GEMM (head-paired): g_Sh fp16
        int idx = bx - bx / 5;
        int nT = idx & 1, hp = (idx >> 1) & 7, z = idx >> 4;
        int c = z % NCH, bb = z / NCH;
        auto src = [&](int tile, int row, int kb) -> const hf* {
            if (tile == 0)
                return g_XW + ((size_t)bb * DIN + hp * 256 + row) * LSEQ + c * CHUNK_ + kb * 32;
            return g_Btf + ((size_t)z * NSTATE + nT * 128 + row) * CHUNK_ + kb * 32;
        };
        gemmT<256, 128, 64, 64, 2>(CHUNK_ / 32, src,
                                   g_Sh + ((size_t)z * NH + 2 * hp) * HD * NSTATE + nT * 128,
                                   nullptr, NSTATE,
                                   nullptr, nullptr, 0, 0, -1, 1.f, 1.f);
    }
}

// ------- inter-chunk scan: g_Sh -> single raw prev fp16 (skip c=0 write) -------
__global__ void k_scan() {
    int idx = blockIdx.x * blockDim.x + threadIdx.x;
    int n = idx & (NSTATE - 1);
    int p = (idx >> 8) & (HD - 1);
    int h = (idx >> 15) & (NH - 1);
    int bb = idx >> 19;
    size_t rest = ((size_t)h * HD + p) * NSTATE + n;
    const size_t stride = (size_t)NH * HD * NSTATE;
    float carry = 0.f;
    for (int c = 0; c < NCH; c++) {
        int zh = (bb * NCH + c) * NH + h;
        size_t off = (size_t)(bb * NCH + c) * stride + rest;
        float sv = __half2float(g_Sh[off]);
        if (c > 0) g_Pf[off] = __float2half_rn(carry);
        carry = carry * g_cd[zh] + sv;
    }
}

// -------- y GEMM (head-paired): inter phase first (raw P), mid-scale, intra phase --------
__global__ void __launch_bounds__(256, 1) k_y() {
    int iT = blockIdx.x, hp = blockIdx.y, z = blockIdx.z;
    int c = z % NCH, bb = z / NCH;
    const int p0kb = iT ? 8 : 4;          // intra-chunk K blocks
    const int interKb = (c > 0) ? 8 : 0;  // inter phase only if prev != 0
    auto src = [&](int tile, int row, int kb) -> const hf* {
        if (kb < interKb) {               // phase A: inter-chunk, n contraction (raw prev)
            int n0 = kb * 32;
            if (tile == 0)
                return g_BCf + src_row(bb, c * CHUNK_ + iT * 128 + row) * (2 * NSTATE) + NSTATE + n0;
            return g_Pf + ((size_t)z * NH + 2 * hp) * HD * NSTATE + (size_t)row * NSTATE + n0;
        }
        int pk = kb - interKb;            // phase B: intra-chunk, k contraction
        if (tile == 0)
            return g_CBf + ((size_t)z * CHUNK_ + iT * 128 + row) * CHUNK_ + pk * 32;
        if (iT)
            return g_XB1 + ((size_t)bb * DIN + hp * 256 + row) * LSEQ + c * CHUNK_ + pk * 32;
        return g_XB0 + (((size_t)bb * DIN + hp * 256 + row) * NCH + c) * 128 + pk * 32;
    };
    int t0 = c * CHUNK_ + iT * 128;
    size_t hb = (size_t)(bb * NH + 2 * hp);
    int zh0 = ((bb * NCH + c) * NH + 2 * hp) * 2 + iT;
    gemmT<128, 256, 64, 64, 1>(interKb + p0kb, src,
                               g_ybuf + (hb * LSEQ + t0) * HD,
                               g_ybuf + ((hb + 1) * LSEQ + t0) * HD, 0,
                               g_E2 + hb * LSEQ + t0,
                               g_E2 + (hb + 1) * LSEQ + t0,
                               0, 0,
                               (c > 0) ? interKb : -1, g_PS[zh0], g_PS[zh0 + 2]);
}

// ---------------- final combine ----------------
__global__ void k_final(const float* __restrict__ x, const float* __restrict__ W,
                        const float* __restrict__ Dp, float* __restrict__ out) {
    int t = blockIdx.x, b = blockIdx.y;
    __shared__ float xs[DIN];
    __shared__ float gate[NH];
    const float* xrow = x + ((size_t)b * LSEQ + t) * DIN;
    for (int d = threadIdx.x; d < DIN; d += 256) xs[d] = xrow[d];
    __syncthreads();
    int warp = threadIdx.x / 32, lane = threadIdx.x % 32;
#pragma unroll
    for (int hh = 0; hh < 2; hh++) {
        int h = warp * 2 + hh;
        const float* wrow = W + (size_t)h * DIN;
        float acc = 0.f;
        for (int d = lane; d < DIN; d += 32) acc += xs[d] * wrow[d];
#pragma unroll
        for (int o = 16; o; o >>= 1) acc += __shfl_down_sync(0xFFFFFFFFu, acc, o);
        if (lane == 0) gate[h] = acc + Dp[h];
    }
    __syncthreads();
    int tb = LSEQ - 1 - t;
    float* orow = out + ((size_t)b * LSEQ + t) * DIN;
    for (int d = threadIdx.x; d < DIN; d += 256) {
        int h = d >> 7, p = d & 127;
        float v = xs[d] * gate[h];
        if (t > 0)
            v += __half2float(g_ybuf[((size_t)(b * NH + h) * LSEQ + (t - 1)) * HD + p]);
        if (tb > 0)
            v += __half2float(g_ybuf[((size_t)((b + 2) * NH + h) * LSEQ + (tb - 1)) * HD + p]);
        orow[d] = v;
    }
}

// ---------------- launch ----------------
extern "C" void kernel_launch(void* const* d_in, const int* in_sizes, int n_in,
                              void* d_out, int out_size) {
    const float* x     = (const float*)d_in[0];
    const float* BC    = (const float*)d_in[1];
    const float* dt    = (const float*)d_in[2];
    const float* A_log = (const float*)d_in[3];
    const float* Dv    = (const float*)d_in[4];
    const float* W     = (const float*)d_in[5];
    float* out = (float*)d_out;

    cudaFuncSetAttribute(k_mid, cudaFuncAttributeMaxDynamicSharedMemorySize, SMEM_MID);
    cudaFuncSetAttribute(k_y,   cudaFuncAttributeMaxDynamicSharedMemorySize, SMEM_YG);

    k_pre     <<<dim3(NCH, NH, NBB), 256>>>(dt, A_log);
    k_split_bc<<<dim3(LSEQ, BSZ), 128>>>(BC);
    k_xsplit  <<<dim3(LSEQ / 32, DIN / 32, NBB), 256>>>(x);
    k_btsplit <<<dim3(8, 8, ZTOT), 256>>>(BC);
    k_mid     <<<1280, 256, SMEM_MID>>>();
    k_scan    <<<(NBB * NH * HD * NSTATE) / 256, 256>>>();
    k_y       <<<dim3(2, NH / 2, ZTOT), 256, SMEM_YG>>>();
    k_final   <<<dim3(LSEQ, BSZ), 256>>>(x, W, Dv, out);
}